// round 13
// baseline (speedup 1.0000x reference)
#include <cuda_runtime.h>
#include <cuda_bf16.h>
#include <cstdint>

// Problem dims (fixed by the reference)
#define T_   2048
#define H_   2048
#define E_   16
#define K_   4
#define I_   1408
#define IS_  2816
#define CAP_ 1024

// ---------------- scratch (device globals; no allocations allowed) ----------
__device__ float g_Gr[E_ * CAP_ * I_];
__device__ float g_Mr[E_ * CAP_ * I_];
__device__ float g_Eout[E_ * CAP_ * H_];
__device__ float g_Gs[T_ * IS_];
__device__ float g_Ms[T_ * IS_];
__device__ int   g_buf[E_ * CAP_];
__device__ int   g_pos[T_ * K_];
__device__ int   g_cnt[E_];
__device__ int   g_ti[T_ * K_];
__device__ float g_tw[T_ * K_];

// bf16 hi parts (main term)
__device__ __align__(128) __nv_bfloat16 g_xH[T_ * H_];
__device__ __align__(128) __nv_bfloat16 g_wgH[E_ * H_ * I_];
__device__ __align__(128) __nv_bfloat16 g_wuH[E_ * H_ * I_];
__device__ __align__(128) __nv_bfloat16 g_wdH[E_ * I_ * H_];
__device__ __align__(128) __nv_bfloat16 g_sgH[H_ * IS_];
__device__ __align__(128) __nv_bfloat16 g_suH[H_ * IS_];
__device__ __align__(128) __nv_bfloat16 g_sdH[IS_ * H_];
__device__ __align__(128) __nv_bfloat16 g_MrH[E_ * CAP_ * I_];
__device__ __align__(128) __nv_bfloat16 g_MsH[T_ * IS_];

// int8 cross-term operands.
// A-side: [rows, 2L] row-major: cols [0,L) = qAh, [L,2L) = qAl (scale sa/256)
// B-side: [N, 2L] n-major:      cols [0,L) = qBl (scale sb/256), [L,2L) = qBh
__device__ __align__(128) signed char g_qX [T_ * 2 * H_];
__device__ __align__(128) signed char g_qMr[E_ * CAP_ * 2 * I_];
__device__ __align__(128) signed char g_qMs[T_ * 2 * IS_];
__device__ __align__(128) signed char g_qwg[E_ * I_ * 2 * H_];
__device__ __align__(128) signed char g_qwu[E_ * I_ * 2 * H_];
__device__ __align__(128) signed char g_qwd[E_ * H_ * 2 * I_];
__device__ __align__(128) signed char g_qsg[IS_ * 2 * H_];
__device__ __align__(128) signed char g_qsu[IS_ * 2 * H_];
__device__ __align__(128) signed char g_qsd[H_ * 2 * IS_];

// scales
__device__ float g_saX[T_];
__device__ float g_saMr[E_ * CAP_];
__device__ float g_saMs[T_];
__device__ float g_sbWg[E_ * I_];
__device__ float g_sbWu[E_ * I_];
__device__ float g_sbWd[E_ * H_];
__device__ float g_sbSg[IS_];
__device__ float g_sbSu[IS_];
__device__ float g_sbSd[H_];

// ======================= helpers ==============================
__device__ __forceinline__ uint32_t smem_u32(const void* p) {
    uint32_t a;
    asm("{ .reg .u64 t; cvta.to.shared.u64 t, %1; cvt.u32.u64 %0, t; }"
        : "=r"(a) : "l"(p));
    return a;
}
__device__ __forceinline__ void ldsm4(uint32_t* r, uint32_t addr) {
    asm volatile("ldmatrix.sync.aligned.m8n8.x4.shared.b16 {%0,%1,%2,%3}, [%4];"
                 : "=r"(r[0]), "=r"(r[1]), "=r"(r[2]), "=r"(r[3]) : "r"(addr));
}
__device__ __forceinline__ void ldsm4t(uint32_t* r, uint32_t addr) {
    asm volatile("ldmatrix.sync.aligned.m8n8.x4.trans.shared.b16 {%0,%1,%2,%3}, [%4];"
                 : "=r"(r[0]), "=r"(r[1]), "=r"(r[2]), "=r"(r[3]) : "r"(addr));
}
__device__ __forceinline__ void mma16816(float* d, const uint32_t* a, const uint32_t* b) {
    asm volatile("mma.sync.aligned.m16n8k16.row.col.f32.bf16.bf16.f32 "
                 "{%0,%1,%2,%3}, {%4,%5,%6,%7}, {%8,%9}, {%0,%1,%2,%3};"
                 : "+f"(d[0]), "+f"(d[1]), "+f"(d[2]), "+f"(d[3])
                 : "r"(a[0]), "r"(a[1]), "r"(a[2]), "r"(a[3]), "r"(b[0]), "r"(b[1]));
}
__device__ __forceinline__ void imma16832(int* d, const uint32_t* a, const uint32_t* b) {
    asm volatile("mma.sync.aligned.m16n8k32.row.col.s32.s8.s8.s32 "
                 "{%0,%1,%2,%3}, {%4,%5,%6,%7}, {%8,%9}, {%0,%1,%2,%3};"
                 : "+r"(d[0]), "+r"(d[1]), "+r"(d[2]), "+r"(d[3])
                 : "r"(a[0]), "r"(a[1]), "r"(a[2]), "r"(a[3]), "r"(b[0]), "r"(b[1]));
}
__device__ __forceinline__ void cpa16(uint32_t dst, const void* src) {
    asm volatile("cp.async.cg.shared.global [%0], [%1], 16;"
                 :: "r"(dst), "l"(src) : "memory");
}
#define CP_COMMIT() asm volatile("cp.async.commit_group;" ::: "memory")
#define CP_WAIT1()  asm volatile("cp.async.wait_group 1;" ::: "memory")

// ---------------- A-side quant: rowmax -> bf16 hi + int8 (hi, lo) -----------
__global__ void aquant_kernel(const float* __restrict__ src, int L,
                              __nv_bfloat16* __restrict__ hi,
                              signed char* __restrict__ q,
                              float* __restrict__ sa)
{
    int row = blockIdx.x;
    const float* s = src + (size_t)row * L;
    __shared__ float red[256];
    float m = 0.f;
    for (int k = threadIdx.x; k < L; k += 256) m = fmaxf(m, fabsf(s[k]));
    red[threadIdx.x] = m; __syncthreads();
    for (int o = 128; o > 0; o >>= 1) {
        if (threadIdx.x < o) red[threadIdx.x] = fmaxf(red[threadIdx.x], red[threadIdx.x + o]);
        __syncthreads();
    }
    float scale = fmaxf(red[0], 1e-30f) / 127.f;
    if (threadIdx.x == 0) sa[row] = scale;
    float inv = 1.f / scale;
    __nv_bfloat16* hrow = hi + (size_t)row * L;
    signed char*   qrow = q  + (size_t)row * 2 * L;
    for (int k = threadIdx.x; k < L; k += 256) {
        float v = s[k];
        __nv_bfloat16 h = __float2bfloat16_rn(v);
        float hf = __bfloat162float(h);
        float lo = v - hf;
        hrow[k] = h;
        int qh = __float2int_rn(hf * inv);          qh = max(-127, min(127, qh));
        int ql = __float2int_rn(lo * inv * 256.f);  ql = max(-127, min(127, ql));
        qrow[k]     = (signed char)qh;
        qrow[L + k] = (signed char)ql;
    }
}

// ---------------- B-side colmax ------------------------------------------------
__global__ void colmax_kernel(const float* __restrict__ src, int L, int N,
                              float* __restrict__ sb)
{
    int n = blockIdx.x * 256 + threadIdx.x;
    int z = blockIdx.y;
    if (n >= N) return;
    const float* s = src + (size_t)z * L * N + n;
    float m = 0.f;
    for (int k = 0; k < L; k++) m = fmaxf(m, fabsf(s[(size_t)k * N]));
    sb[z * N + n] = fmaxf(m, 1e-30f) / 127.f;
}

// ---------------- B-side quant + transpose -----------------------------------
// src [z][L][N] fp32 -> hi [z][L][N] bf16, qt [z][N][2L] int8 (lo at k, hi at L+k)
__global__ void bquant_kernel(const float* __restrict__ src, int L, int N,
                              const float* __restrict__ sb,
                              __nv_bfloat16* __restrict__ hi,
                              signed char* __restrict__ qt)
{
    int z = blockIdx.z;
    int n0 = blockIdx.x * 32, k0 = blockIdx.y * 32;
    const float* s = src + (size_t)z * L * N;
    __nv_bfloat16* h = hi + (size_t)z * L * N;
    signed char* qz = qt + (size_t)z * N * 2 * L;
    __shared__ signed char th[32][33], tl[32][33];   // [k][n]
    int tx = threadIdx.x;
    int n = n0 + tx;
    float invs = 1.f / sb[z * N + n];
    for (int r = threadIdx.y; r < 32; r += 8) {
        int k = k0 + r;
        float v = s[(size_t)k * N + n];
        __nv_bfloat16 hb = __float2bfloat16_rn(v);
        float hf = __bfloat162float(hb);
        h[(size_t)k * N + n] = hb;
        int qh = __float2int_rn(hf * invs);                 qh = max(-127, min(127, qh));
        int ql = __float2int_rn((v - hf) * invs * 256.f);   ql = max(-127, min(127, ql));
        th[r][tx] = (signed char)qh;
        tl[r][tx] = (signed char)ql;
    }
    __syncthreads();
    for (int r = threadIdx.y; r < 32; r += 8) {
        int n2 = n0 + r;
        signed char* row = qz + (size_t)n2 * 2 * L;
        row[(size_t)k0 + tx]     = tl[tx][r];   // Bl
        row[(size_t)L + k0 + tx] = th[tx][r];   // Bh
    }
}

// ---------------- gate: logits -> softmax-topk -> normalized weights --------
__global__ void gate_topk_kernel(const float* __restrict__ x,
                                 const float* __restrict__ gw)
{
    int t = blockIdx.x;
    const float* xr = x + (size_t)t * H_;
    float acc[E_];
#pragma unroll
    for (int e = 0; e < E_; e++) acc[e] = 0.f;
    for (int h = threadIdx.x; h < H_; h += 256) {
        float xv = xr[h];
#pragma unroll
        for (int e = 0; e < E_; e++) acc[e] += xv * gw[e * H_ + h];
    }
#pragma unroll
    for (int e = 0; e < E_; e++) {
#pragma unroll
        for (int o = 16; o > 0; o >>= 1)
            acc[e] += __shfl_down_sync(0xffffffffu, acc[e], o);
    }
    __shared__ float sw[8][E_];
    int warp = threadIdx.x >> 5, lane = threadIdx.x & 31;
    if (lane == 0) {
#pragma unroll
        for (int e = 0; e < E_; e++) sw[warp][e] = acc[e];
    }
    __syncthreads();
    if (threadIdx.x == 0) {
        float lg[E_];
#pragma unroll
        for (int e = 0; e < E_; e++) {
            float s = 0.f;
            for (int w = 0; w < 8; w++) s += sw[w][e];
            lg[e] = s;
        }
        float m = lg[0];
#pragma unroll
        for (int e = 1; e < E_; e++) m = fmaxf(m, lg[e]);
        bool used[E_];
#pragma unroll
        for (int e = 0; e < E_; e++) used[e] = false;
        float wsel[K_]; int isel[K_]; float s = 0.f;
#pragma unroll
        for (int k = 0; k < K_; k++) {
            int best = 0; float bv = -1e30f;
            for (int e = 0; e < E_; e++)
                if (!used[e] && lg[e] > bv) { bv = lg[e]; best = e; }
            used[best] = true;
            isel[k] = best;
            wsel[k] = expf(lg[best] - m);
            s += wsel[k];
        }
        float inv = 1.f / s;
#pragma unroll
        for (int k = 0; k < K_; k++) {
            g_ti[t * K_ + k] = isel[k];
            g_tw[t * K_ + k] = wsel[k] * inv;
        }
    }
}

// ---------------- dispatch: stable rank within each expert -------------------
__global__ void dispatch_kernel()
{
    int e   = blockIdx.x;
    int tid = threadIdx.x;
    const int PER = (T_ * K_) / 256;
    int base = tid * PER;
    int c = 0;
    for (int j = 0; j < PER; j++)
        if (g_ti[base + j] == e) c++;
    __shared__ int ps[256];
    ps[tid] = c;
    __syncthreads();
    for (int off = 1; off < 256; off <<= 1) {
        int v = 0;
        if (tid >= off) v = ps[tid - off];
        __syncthreads();
        ps[tid] += v;
        __syncthreads();
    }
    int total = ps[255];
    int rank  = ps[tid] - c;
    for (int j = 0; j < PER; j++) {
        int idx = base + j;
        if (g_ti[idx] == e) {
            if (rank < CAP_) {
                g_buf[e * CAP_ + rank] = idx >> 2;
                g_pos[idx] = rank;
            } else {
                g_pos[idx] = -1;
            }
            rank++;
        }
    }
    if (tid == 0) g_cnt[e] = total < CAP_ ? total : CAP_;
}

// ====== GEMM: bf16 main (AhBh) + int8 IMMA crosses (AhBl + AlBh), Kc=32 ======
// tile 128x128, 256 threads, 8 warps (warp tile 32x64), 3-stage cp.async ring.
#define O_ABF 0
#define O_BBF 10240
#define O_AI8 18944
#define O_BI8 29184
#define STAGE_SZ 39424
#define NSTAGE 3
#define SM_DYN (NSTAGE * STAGE_SZ)   // 118272

template <bool GATHER, int EPI>
__global__ __launch_bounds__(256)
void mma_gemm(const __nv_bfloat16* __restrict__ AH, const signed char* __restrict__ QA,
              const float* __restrict__ SA,
              const __nv_bfloat16* __restrict__ BH, const signed char* __restrict__ QB,
              const float* __restrict__ SB,
              float* __restrict__ Cf, const float* __restrict__ G,
              const int* __restrict__ rows, const int* __restrict__ cnt,
              int Mfull, int N, int Kd,
              long long sA, long long sB, int saStride, long long sC)
{
    extern __shared__ char dsm[];
    const int z = blockIdx.z;
    int Mz = Mfull;
    if (cnt) { int c = cnt[z]; Mz = c < Mfull ? c : Mfull; }
    const int yblk = blockIdx.y * 128;
    if (yblk >= Mz) return;
    const int xblk = blockIdx.x * 128;

    const uint32_t sm = smem_u32(dsm);
    const int tid = threadIdx.x;
    const int wid = tid >> 5;
    const int lid = tid & 31;

    // ---- cp.async source/dst plan (8 x cpa16 per thread per stage) ----
    // A (bf16 + int8): thread -> row tid>>1, half tid&1
    const char *aBfSrc, *aQSrc;
    uint32_t aBfDst, aQDst;
    {
        int row = tid >> 1, h = tid & 1;
        int mg = yblk + row;
        long long r;
        if (GATHER) r = (mg < Mz) ? (long long)rows[z * CAP_ + mg] : 0;
        else        r = (mg < Mfull) ? mg : 0;
        const __nv_bfloat16* bh = AH + (GATHER ? 0 : (size_t)z * sA) + r * (long long)Kd;
        const signed char*   bq = QA + (GATHER ? 0 : (size_t)z * 2 * sA) + r * (long long)(2 * Kd);
        aBfSrc = (const char*)bh + h * 32;            // + ch*64
        aQSrc  = (const char*)bq + (h ? Kd : 0);      // + ch*32
        aBfDst = (uint32_t)row * 80 + h * 32;
        aQDst  = (uint32_t)row * 80 + h * 32;
    }
    // B bf16: thread -> k tid>>3, seg tid&7
    const char* bBfSrc; uint32_t bBfDst;
    {
        int k = tid >> 3, seg = tid & 7;
        bBfSrc = (const char*)(BH + (size_t)z * sB + (size_t)k * N + xblk) + seg * 32;  // + ch*N*64
        bBfDst = (uint32_t)k * 272 + seg * 32;
    }
    // B int8: thread -> n tid>>1, half tid&1
    const char* bQSrc; uint32_t bQDst;
    {
        int n = tid >> 1, h = tid & 1;
        bQSrc = (const char*)(QB + (size_t)z * 2 * sB + (size_t)(xblk + n) * 2 * Kd) + (h ? Kd : 0);  // + ch*32
        bQDst = (uint32_t)n * 80 + h * 32;
    }

    const int nch = Kd / 32;
    auto issueStage = [&](int ch) {
        if (ch >= nch) return;
        const uint32_t st = sm + (uint32_t)(ch % NSTAGE) * STAGE_SZ;
        const char* a0 = aBfSrc + (size_t)ch * 64;
        const char* b0 = bBfSrc + (size_t)ch * (size_t)N * 64;
        const char* a1 = aQSrc + (size_t)ch * 32;
        const char* b1 = bQSrc + (size_t)ch * 32;
        cpa16(st + O_ABF + aBfDst,      a0);
        cpa16(st + O_ABF + aBfDst + 16, a0 + 16);
        cpa16(st + O_BBF + bBfDst,      b0);
        cpa16(st + O_BBF + bBfDst + 16, b0 + 16);
        cpa16(st + O_AI8 + aQDst,       a1);
        cpa16(st + O_AI8 + aQDst + 16,  a1 + 16);
        cpa16(st + O_BI8 + bQDst,       b1);
        cpa16(st + O_BI8 + bQDst + 16,  b1 + 16);
    };

    // ---- warp compute geometry (warp tile 32x64) ----
    const int wm = wid & 3;
    const int wn = wid >> 2;
    const int l15 = lid & 15, lh = lid >> 4;
    const uint32_t aLaneBf = O_ABF + (uint32_t)(wm * 32 + l15) * 80 + lh * 16;
    const uint32_t bLaneBf = O_BBF + (uint32_t)l15 * 272 + (uint32_t)(wn * 64 + lh * 8) * 2;
    const uint32_t aLaneI8 = O_AI8 + (uint32_t)(wm * 32 + l15) * 80 + lh * 16;
    // int8 B ldsm4 lane base (covers 2 n8-tiles per issue)
    const uint32_t bLaneI8 = O_BI8
        + (uint32_t)(wn * 64 + ((lid >> 4) & 1) * 8 + (lid & 7)) * 80
        + ((lid >> 3) & 1) * 16;

    float facc[2][8][4];
    int   iacc[2][8][4];
#pragma unroll
    for (int mt = 0; mt < 2; mt++)
#pragma unroll
        for (int j = 0; j < 8; j++)
#pragma unroll
            for (int q = 0; q < 4; q++) { facc[mt][j][q] = 0.f; iacc[mt][j][q] = 0; }

    issueStage(0); CP_COMMIT();
    issueStage(1); CP_COMMIT();

    for (int ch = 0; ch < nch; ch++) {
        CP_WAIT1();
        __syncthreads();
        issueStage(ch + 2);
        CP_COMMIT();

        const uint32_t base = sm + (uint32_t)(ch % NSTAGE) * STAGE_SZ;

        // ---- bf16 main term ----
#pragma unroll
        for (int kk = 0; kk < 2; kk++) {
            uint32_t ah[2][4], bh[4][4];
#pragma unroll
            for (int mt = 0; mt < 2; mt++)
                ldsm4(ah[mt], base + aLaneBf + mt * 16 * 80 + kk * 32);
#pragma unroll
            for (int nt = 0; nt < 4; nt++)
                ldsm4t(bh[nt], base + bLaneBf + kk * 16 * 272 + nt * 32);
#pragma unroll
            for (int mt = 0; mt < 2; mt++)
#pragma unroll
                for (int nt = 0; nt < 4; nt++) {
                    mma16816(facc[mt][2 * nt],     ah[mt], &bh[nt][0]);
                    mma16816(facc[mt][2 * nt + 1], ah[mt], &bh[nt][2]);
                }
        }

        // ---- int8 cross terms ----
        uint32_t ahq[2][4], alq[2][4];
#pragma unroll
        for (int mt = 0; mt < 2; mt++) {
            ldsm4(ahq[mt], base + aLaneI8 + mt * 16 * 80);
            ldsm4(alq[mt], base + aLaneI8 + mt * 16 * 80 + 32);
        }
        uint32_t blq[8][2], bhq[8][2];
#pragma unroll
        for (int p = 0; p < 4; p++) {
            uint32_t r[4];
            ldsm4(r, base + bLaneI8 + p * 1280);        // Bl (cols 0-31)
            blq[2 * p][0] = r[0]; blq[2 * p][1] = r[1];
            blq[2 * p + 1][0] = r[2]; blq[2 * p + 1][1] = r[3];
            ldsm4(r, base + bLaneI8 + p * 1280 + 32);   // Bh (cols 32-63)
            bhq[2 * p][0] = r[0]; bhq[2 * p][1] = r[1];
            bhq[2 * p + 1][0] = r[2]; bhq[2 * p + 1][1] = r[3];
        }
#pragma unroll
        for (int mt = 0; mt < 2; mt++)
#pragma unroll
            for (int j = 0; j < 8; j++) {
                imma16832(iacc[mt][j], ahq[mt], blq[j]);
                imma16832(iacc[mt][j], alq[mt], bhq[j]);
            }
    }

    // ---- epilogue: merge fp32 main + scaled int32 crosses ----
    const int group = lid >> 2, tig = lid & 3;
#pragma unroll
    for (int mt = 0; mt < 2; mt++) {
        int r0 = yblk + wm * 32 + mt * 16 + group;
#pragma unroll
        for (int half = 0; half < 2; half++) {
            int r = r0 + half * 8;
            if (r < Mz) {
                int arow;
                if (GATHER) arow = rows[z * CAP_ + r];
                else        arow = z * saStride + r;
                float sav = SA[arow] * (1.f / 256.f);
                size_t off0 = (size_t)z * sC + (size_t)r * N;
#pragma unroll
                for (int j = 0; j < 8; j++) {
                    int col = xblk + wn * 64 + j * 8 + 2 * tig;
                    float sb0 = SB[z * N + col];
                    float sb1 = SB[z * N + col + 1];
                    float d0 = facc[mt][j][2 * half]     + (float)iacc[mt][j][2 * half]     * sav * sb0;
                    float d1 = facc[mt][j][2 * half + 1] + (float)iacc[mt][j][2 * half + 1] * sav * sb1;
                    size_t off = off0 + col;
                    if (EPI == 1) {
                        float2 g = *(const float2*)&G[off];
                        d0 *= g.x / (1.f + __expf(-g.x));
                        d1 *= g.y / (1.f + __expf(-g.y));
                    }
                    *(float2*)&Cf[off] = make_float2(d0, d1);
                }
            }
        }
    }
}

// ---------------- combine: out[t] += sum_k w * eout[e_k, pos_k] --------------
__global__ void combine_kernel(float* __restrict__ out)
{
    int t   = blockIdx.x;
    int tid = threadIdx.x;
    const float* rp[K_]; float w[K_]; bool v[K_];
#pragma unroll
    for (int k = 0; k < K_; k++) {
        int p = g_pos[t * K_ + k];
        int e = g_ti[t * K_ + k];
        w[k]  = g_tw[t * K_ + k];
        v[k]  = (p >= 0);
        int pc = p < 0 ? 0 : p;
        rp[k] = g_Eout + ((size_t)e * CAP_ + pc) * H_;
    }
#pragma unroll
    for (int j = 0; j < 2; j++) {
        int c4 = tid + j * 256;
        size_t off = (size_t)t * H_ + c4 * 4;
        float4 a = *(float4*)&out[off];
#pragma unroll
        for (int k = 0; k < K_; k++) {
            if (v[k]) {
                float4 xv = *(const float4*)&rp[k][c4 * 4];
                a.x += w[k] * xv.x; a.y += w[k] * xv.y;
                a.z += w[k] * xv.z; a.w += w[k] * xv.w;
            }
        }
        *(float4*)&out[off] = a;
    }
}

// ---------------- launch ------------------------------------------------------
extern "C" void kernel_launch(void* const* d_in, const int* in_sizes, int n_in,
                              void* d_out, int out_size)
{
    const float* x       = (const float*)d_in[0];
    const float* gate_w  = (const float*)d_in[1];
    const float* w_gate  = (const float*)d_in[2];
    const float* w_up    = (const float*)d_in[3];
    const float* w_down  = (const float*)d_in[4];
    const float* sw_gate = (const float*)d_in[5];
    const float* sw_up   = (const float*)d_in[6];
    const float* sw_down = (const float*)d_in[7];
    float* out = (float*)d_out;

    float *Gr, *Mr, *Eo, *Gs, *Ms;
    int *buf, *cnt;
    __nv_bfloat16 *xH, *wgH, *wuH, *wdH, *sgH, *suH, *sdH, *MrH, *MsH;
    signed char *qX, *qMr, *qMs, *qwg, *qwu, *qwd, *qsg, *qsu, *qsd;
    float *saX, *saMr, *saMs, *sbWg, *sbWu, *sbWd, *sbSg, *sbSu, *sbSd;

    cudaGetSymbolAddress((void**)&Gr,  g_Gr);
    cudaGetSymbolAddress((void**)&Mr,  g_Mr);
    cudaGetSymbolAddress((void**)&Eo,  g_Eout);
    cudaGetSymbolAddress((void**)&Gs,  g_Gs);
    cudaGetSymbolAddress((void**)&Ms,  g_Ms);
    cudaGetSymbolAddress((void**)&buf, g_buf);
    cudaGetSymbolAddress((void**)&cnt, g_cnt);
    cudaGetSymbolAddress((void**)&xH,  g_xH);
    cudaGetSymbolAddress((void**)&wgH, g_wgH);
    cudaGetSymbolAddress((void**)&wuH, g_wuH);
    cudaGetSymbolAddress((void**)&wdH, g_wdH);
    cudaGetSymbolAddress((void**)&sgH, g_sgH);
    cudaGetSymbolAddress((void**)&suH, g_suH);
    cudaGetSymbolAddress((void**)&sdH, g_sdH);
    cudaGetSymbolAddress((void**)&MrH, g_MrH);
    cudaGetSymbolAddress((void**)&MsH, g_MsH);
    cudaGetSymbolAddress((void**)&qX,  g_qX);
    cudaGetSymbolAddress((void**)&qMr, g_qMr);
    cudaGetSymbolAddress((void**)&qMs, g_qMs);
    cudaGetSymbolAddress((void**)&qwg, g_qwg);
    cudaGetSymbolAddress((void**)&qwu, g_qwu);
    cudaGetSymbolAddress((void**)&qwd, g_qwd);
    cudaGetSymbolAddress((void**)&qsg, g_qsg);
    cudaGetSymbolAddress((void**)&qsu, g_qsu);
    cudaGetSymbolAddress((void**)&qsd, g_qsd);
    cudaGetSymbolAddress((void**)&saX,  g_saX);
    cudaGetSymbolAddress((void**)&saMr, g_saMr);
    cudaGetSymbolAddress((void**)&saMs, g_saMs);
    cudaGetSymbolAddress((void**)&sbWg, g_sbWg);
    cudaGetSymbolAddress((void**)&sbWu, g_sbWu);
    cudaGetSymbolAddress((void**)&sbWd, g_sbWd);
    cudaGetSymbolAddress((void**)&sbSg, g_sbSg);
    cudaGetSymbolAddress((void**)&sbSu, g_sbSu);
    cudaGetSymbolAddress((void**)&sbSd, g_sbSd);

    cudaFuncSetAttribute(mma_gemm<true, 0>,  cudaFuncAttributeMaxDynamicSharedMemorySize, SM_DYN);
    cudaFuncSetAttribute(mma_gemm<true, 1>,  cudaFuncAttributeMaxDynamicSharedMemorySize, SM_DYN);
    cudaFuncSetAttribute(mma_gemm<false, 0>, cudaFuncAttributeMaxDynamicSharedMemorySize, SM_DYN);
    cudaFuncSetAttribute(mma_gemm<false, 1>, cudaFuncAttributeMaxDynamicSharedMemorySize, SM_DYN);

    dim3 b328(32, 8);

    // 0) weight colmax + quant/transpose; activation quant
    colmax_kernel<<<dim3((I_ + 255) / 256, E_), 256>>>(w_gate, H_, I_, sbWg);
    colmax_kernel<<<dim3((I_ + 255) / 256, E_), 256>>>(w_up,   H_, I_, sbWu);
    colmax_kernel<<<dim3((H_ + 255) / 256, E_), 256>>>(w_down, I_, H_, sbWd);
    colmax_kernel<<<dim3((IS_ + 255) / 256, 1), 256>>>(sw_gate, H_, IS_, sbSg);
    colmax_kernel<<<dim3((IS_ + 255) / 256, 1), 256>>>(sw_up,   H_, IS_, sbSu);
    colmax_kernel<<<dim3((H_ + 255) / 256, 1), 256>>>(sw_down, IS_, H_, sbSd);

    bquant_kernel<<<dim3(I_ / 32, H_ / 32, E_), b328>>>(w_gate, H_, I_, sbWg, wgH, qwg);
    bquant_kernel<<<dim3(I_ / 32, H_ / 32, E_), b328>>>(w_up,   H_, I_, sbWu, wuH, qwu);
    bquant_kernel<<<dim3(H_ / 32, I_ / 32, E_), b328>>>(w_down, I_, H_, sbWd, wdH, qwd);
    bquant_kernel<<<dim3(IS_ / 32, H_ / 32, 1), b328>>>(sw_gate, H_, IS_, sbSg, sgH, qsg);
    bquant_kernel<<<dim3(IS_ / 32, H_ / 32, 1), b328>>>(sw_up,   H_, IS_, sbSu, suH, qsu);
    bquant_kernel<<<dim3(H_ / 32, IS_ / 32, 1), b328>>>(sw_down, IS_, H_, sbSd, sdH, qsd);

    aquant_kernel<<<T_, 256>>>(x, H_, xH, qX, saX);

    // 1) routing
    gate_topk_kernel<<<T_, 256>>>(x, gate_w);
    dispatch_kernel<<<E_, 256>>>();

    // 2) routed experts
    dim3 g1(I_ / 128, CAP_ / 128, E_);
    mma_gemm<true, 0><<<g1, 256, SM_DYN>>>(xH, qX, saX, wgH, qwg, sbWg, Gr, nullptr,
        buf, cnt, CAP_, I_, H_, 0, (long long)H_ * I_, 0, (long long)CAP_ * I_);
    mma_gemm<true, 1><<<g1, 256, SM_DYN>>>(xH, qX, saX, wuH, qwu, sbWu, Mr, Gr,
        buf, cnt, CAP_, I_, H_, 0, (long long)H_ * I_, 0, (long long)CAP_ * I_);
    aquant_kernel<<<E_ * CAP_, 256>>>(Mr, I_, MrH, qMr, saMr);
    dim3 g2(H_ / 128, CAP_ / 128, E_);
    mma_gemm<false, 0><<<g2, 256, SM_DYN>>>(MrH, qMr, saMr, wdH, qwd, sbWd, Eo, nullptr,
        nullptr, cnt, CAP_, H_, I_, (long long)CAP_ * I_, (long long)I_ * H_, CAP_, (long long)CAP_ * H_);

    // 3) shared expert
    dim3 g3(IS_ / 128, T_ / 128, 1);
    mma_gemm<false, 0><<<g3, 256, SM_DYN>>>(xH, qX, saX, sgH, qsg, sbSg, Gs, nullptr,
        nullptr, nullptr, T_, IS_, H_, 0, 0, 0, 0);
    mma_gemm<false, 1><<<g3, 256, SM_DYN>>>(xH, qX, saX, suH, qsu, sbSu, Ms, Gs,
        nullptr, nullptr, T_, IS_, H_, 0, 0, 0, 0);
    aquant_kernel<<<T_, 256>>>(Ms, IS_, MsH, qMs, saMs);
    dim3 g4(H_ / 128, T_ / 128, 1);
    mma_gemm<false, 0><<<g4, 256, SM_DYN>>>(MsH, qMs, saMs, sdH, qsd, sbSd, out, nullptr,
        nullptr, nullptr, T_, H_, IS_, 0, 0, 0, 0);

    // 4) combine routed contributions (deterministic gather, no atomics)
    combine_kernel<<<T_, 256>>>(out);
}